// round 3
// baseline (speedup 1.0000x reference)
#include <cuda_runtime.h>
#include <math.h>

// Problem constants
#define Bz 64
#define Hd 512
#define Ed 512
#define Sl 64
#define Tt 32
#define BH (Bz*Hd)

// Output layout (flattened, in reference return order):
// outputs [T,B,H] @0 (1048576), attns [T,B,S] (131072), hf [2,B,H], cf [2,B,H], feedf [B,H]
#define OFF_AT 1048576
#define OFF_HF 1179648
#define OFF_CF 1245184
#define OFF_FF 1310720

// Persistent decoder state (no device allocation allowed -> __device__ globals)
__device__ float g_h0[2][BH];   // layer-0 hidden, ping-pong by t parity
__device__ float g_h1[2][BH];   // layer-1 hidden, ping-pong
__device__ float g_c0[BH];
__device__ float g_c1[BH];
__device__ float g_feed[BH];
__device__ float g_q[BH];       // h1n @ Wa^T
__device__ float g_cvec[BH];    // attention context vector

__device__ __forceinline__ float sigf(float x){ return 1.0f/(1.0f+__expf(-x)); }

// ---------------------------------------------------------------------------
// Init: load h0/c0/input_feed into persistent state (runs every launch ->
// deterministic across graph replays).
// ---------------------------------------------------------------------------
__global__ void kInit(const float* __restrict__ h0, const float* __restrict__ c0,
                      const float* __restrict__ feed){
    int i = blockIdx.x*blockDim.x + threadIdx.x;
    if (i < BH){
        g_h0[0][i] = h0[i];       g_h1[0][i] = h0[BH + i];
        g_c0[i]    = c0[i];       g_c1[i]    = c0[BH + i];
        g_feed[i]  = feed[i];
    }
}

// ---------------------------------------------------------------------------
// Kernel A: gates0 = [emb(tok) | feed] @ W_ih0^T + h0_prev @ W_hh0^T + biases,
// then LSTM cell 0. One block per 4 hidden units (grid=128). Block computes a
// 64b x 16j gate tile (j = the 4 gates x 4 hidden units), K = 512+512+512.
// Micro-tile 2b x 2j per thread: 4 FFMA per 2 LDS -> FFMA-pipe bound.
// ---------------------------------------------------------------------------
__global__ __launch_bounds__(256) void kA(
    const int* __restrict__ toks_all, const float* __restrict__ emb,
    const float* __restrict__ Wih, const float* __restrict__ Whh,
    const float* __restrict__ bih, const float* __restrict__ bhh,
    float* __restrict__ dout, int t)
{
    __shared__ float xs[32][64];   // [k][b]
    __shared__ float ws[32][16];   // [k][j-col]
    __shared__ float Gs[64][17];   // gate values for cell phase
    __shared__ int   toks[64];
    const int p   = t & 1;
    const int tid = threadIdx.x;
    const int hh0 = blockIdx.x << 2;

    if (tid < 64) toks[tid] = toks_all[t*Bz + tid];

    const int tb = tid & 31, tc = tid >> 5;      // 32 b-pairs x 8 j-pairs
    const int c0i = 2*tc, c1i = c0i+1;
    const int j0 = (c0i>>2)*Hd + hh0 + (c0i&3);  // c = gate*4 + u  -> j = gate*512 + hh0 + u
    const int j1 = (c1i>>2)*Hd + hh0 + (c1i&3);
    float a00,a01,a10,a11;
    { float bj0 = bih[j0]+bhh[j0], bj1 = bih[j1]+bhh[j1]; a00=a10=bj0; a01=a11=bj1; }

    const int lb  = tid >> 2;            // x loader: b row
    const int lk  = (tid & 3) << 3;      // 8 consecutive k
    const int lj  = tid >> 4;            // w loader: col 0..15
    const int lk2 = (tid & 15) << 1;     // 2 consecutive k
    const int ljj = (lj>>2)*Hd + hh0 + (lj&3);
    const float* h0p = g_h0[p];
    __syncthreads();  // toks ready

    for (int kc = 0; kc < 48; ++kc) {
        const float* xsrc;
        if (kc < 16)      xsrc = emb    + (size_t)toks[lb]*Ed + (kc<<5);
        else if (kc < 32) xsrc = g_feed + lb*Hd + ((kc-16)<<5);
        else              xsrc = h0p    + lb*Hd + ((kc-32)<<5);
        float4 v0 = *(const float4*)(xsrc + lk);
        float4 v1 = *(const float4*)(xsrc + lk + 4);
        const float* wsrc = (kc < 32) ? (Wih + (size_t)ljj*1024 + (kc<<5))
                                      : (Whh + (size_t)ljj*512  + ((kc-32)<<5));
        float2 wv = *(const float2*)(wsrc + lk2);
        xs[lk+0][lb]=v0.x; xs[lk+1][lb]=v0.y; xs[lk+2][lb]=v0.z; xs[lk+3][lb]=v0.w;
        xs[lk+4][lb]=v1.x; xs[lk+5][lb]=v1.y; xs[lk+6][lb]=v1.z; xs[lk+7][lb]=v1.w;
        ws[lk2][lj]=wv.x;  ws[lk2+1][lj]=wv.y;
        __syncthreads();
        #pragma unroll
        for (int kk=0; kk<32; ++kk) {
            float2 xv = *(const float2*)&xs[kk][tb<<1];
            float2 w2 = *(const float2*)&ws[kk][tc<<1];
            a00 = fmaf(xv.x, w2.x, a00);
            a01 = fmaf(xv.x, w2.y, a01);
            a10 = fmaf(xv.y, w2.x, a10);
            a11 = fmaf(xv.y, w2.y, a11);
        }
        __syncthreads();
    }
    Gs[tb*2  ][c0i]=a00; Gs[tb*2  ][c1i]=a01;
    Gs[tb*2+1][c0i]=a10; Gs[tb*2+1][c1i]=a11;
    __syncthreads();

    // Cell phase: 64b x 4u
    const int b = tid & 63, u = tid >> 6;
    float iv=Gs[b][u], fv=Gs[b][4+u], gv=Gs[b][8+u], ov=Gs[b][12+u];
    const int hidx = hh0 + u;
    float cold = g_c0[b*Hd + hidx];
    float cn = sigf(fv)*cold + sigf(iv)*tanhf(gv);
    float hn = sigf(ov)*tanhf(cn);
    g_c0[b*Hd+hidx]      = cn;
    g_h0[p^1][b*Hd+hidx] = hn;
    if (t == Tt-1){
        dout[OFF_HF + b*Hd + hidx] = hn;
        dout[OFF_CF + b*Hd + hidx] = cn;
    }
}

// ---------------------------------------------------------------------------
// Kernel B: gates1 = h0n @ W_ih1^T + h1_prev @ W_hh1^T + biases, LSTM cell 1.
// ---------------------------------------------------------------------------
__global__ __launch_bounds__(256) void kB(
    const float* __restrict__ Wih, const float* __restrict__ Whh,
    const float* __restrict__ bih, const float* __restrict__ bhh,
    float* __restrict__ dout, int t)
{
    __shared__ float xs[32][64];
    __shared__ float ws[32][16];
    __shared__ float Gs[64][17];
    const int p   = t & 1;
    const int tid = threadIdx.x;
    const int hh0 = blockIdx.x << 2;
    const int tb = tid & 31, tc = tid >> 5;
    const int c0i = 2*tc, c1i = c0i+1;
    const int j0 = (c0i>>2)*Hd + hh0 + (c0i&3);
    const int j1 = (c1i>>2)*Hd + hh0 + (c1i&3);
    float a00,a01,a10,a11;
    { float bj0 = bih[j0]+bhh[j0], bj1 = bih[j1]+bhh[j1]; a00=a10=bj0; a01=a11=bj1; }
    const int lb  = tid >> 2, lk  = (tid & 3) << 3;
    const int lj  = tid >> 4, lk2 = (tid & 15) << 1;
    const int ljj = (lj>>2)*Hd + hh0 + (lj&3);
    const float* x0 = g_h0[p^1];   // h0n from this step
    const float* x1 = g_h1[p];     // h1 from previous step

    for (int kc = 0; kc < 32; ++kc) {
        const float* xsrc = (kc<16) ? x0 + lb*Hd + (kc<<5) : x1 + lb*Hd + ((kc-16)<<5);
        float4 v0 = *(const float4*)(xsrc + lk);
        float4 v1 = *(const float4*)(xsrc + lk + 4);
        const float* wsrc = (kc<16) ? (Wih + (size_t)ljj*512 + (kc<<5))
                                    : (Whh + (size_t)ljj*512 + ((kc-16)<<5));
        float2 wv = *(const float2*)(wsrc + lk2);
        xs[lk+0][lb]=v0.x; xs[lk+1][lb]=v0.y; xs[lk+2][lb]=v0.z; xs[lk+3][lb]=v0.w;
        xs[lk+4][lb]=v1.x; xs[lk+5][lb]=v1.y; xs[lk+6][lb]=v1.z; xs[lk+7][lb]=v1.w;
        ws[lk2][lj]=wv.x;  ws[lk2+1][lj]=wv.y;
        __syncthreads();
        #pragma unroll
        for (int kk=0; kk<32; ++kk) {
            float2 xv = *(const float2*)&xs[kk][tb<<1];
            float2 w2 = *(const float2*)&ws[kk][tc<<1];
            a00 = fmaf(xv.x, w2.x, a00);
            a01 = fmaf(xv.x, w2.y, a01);
            a10 = fmaf(xv.y, w2.x, a10);
            a11 = fmaf(xv.y, w2.y, a11);
        }
        __syncthreads();
    }
    Gs[tb*2  ][c0i]=a00; Gs[tb*2  ][c1i]=a01;
    Gs[tb*2+1][c0i]=a10; Gs[tb*2+1][c1i]=a11;
    __syncthreads();

    const int b = tid & 63, u = tid >> 6;
    float iv=Gs[b][u], fv=Gs[b][4+u], gv=Gs[b][8+u], ov=Gs[b][12+u];
    const int hidx = hh0 + u;
    float cold = g_c1[b*Hd + hidx];
    float cn = sigf(fv)*cold + sigf(iv)*tanhf(gv);
    float hn = sigf(ov)*tanhf(cn);
    g_c1[b*Hd+hidx]      = cn;
    g_h1[p^1][b*Hd+hidx] = hn;
    if (t == Tt-1){
        dout[OFF_HF + BH + b*Hd + hidx] = hn;
        dout[OFF_CF + BH + b*Hd + hidx] = cn;
    }
}

// ---------------------------------------------------------------------------
// Kernel Q: q = h1n @ Wa^T   ([64,512], K=512). grid=64, tile 64b x 8j.
// ---------------------------------------------------------------------------
__global__ __launch_bounds__(256) void kQ(const float* __restrict__ Wa, int t)
{
    __shared__ float xs[32][64];
    __shared__ float ws[32][8];
    const int tid = threadIdx.x;
    const int jb  = blockIdx.x << 3;
    const int tb = tid & 31, tc = tid >> 5;
    const int lb = tid >> 2, lk = (tid & 3) << 3;
    const int lj = tid >> 5, lk2 = tid & 31;
    float a0=0.f, a1=0.f;
    const float* h1n = g_h1[(t&1)^1];
    for (int kc=0; kc<16; ++kc){
        const float* xsrc = h1n + lb*Hd + (kc<<5);
        float4 v0 = *(const float4*)(xsrc+lk);
        float4 v1 = *(const float4*)(xsrc+lk+4);
        float wv = Wa[(size_t)(jb+lj)*Hd + (kc<<5) + lk2];
        xs[lk+0][lb]=v0.x; xs[lk+1][lb]=v0.y; xs[lk+2][lb]=v0.z; xs[lk+3][lb]=v0.w;
        xs[lk+4][lb]=v1.x; xs[lk+5][lb]=v1.y; xs[lk+6][lb]=v1.z; xs[lk+7][lb]=v1.w;
        ws[lk2][lj]=wv;
        __syncthreads();
        #pragma unroll
        for (int kk=0; kk<32; ++kk){
            float2 xv = *(const float2*)&xs[kk][tb<<1];
            float w  = ws[kk][tc];
            a0 = fmaf(xv.x, w, a0);
            a1 = fmaf(xv.y, w, a1);
        }
        __syncthreads();
    }
    g_q[(tb*2  )*Hd + jb + tc] = a0;
    g_q[(tb*2+1)*Hd + jb + tc] = a1;
}

// ---------------------------------------------------------------------------
// Kernel S: per-batch attention: scores = q . context, softmax, cvec.
// grid=64 (one block per batch). Writes attns to d_out and g_cvec.
// ---------------------------------------------------------------------------
__global__ __launch_bounds__(256) void kS(const float* __restrict__ ctx,
                                          float* __restrict__ dout, int t)
{
    const int b = blockIdx.x;
    const int tid = threadIdx.x;
    __shared__ float qs[512];
    __shared__ float sc[64];
    __shared__ float al[64];
    qs[tid]     = g_q[b*Hd + tid];
    qs[tid+256] = g_q[b*Hd + 256 + tid];
    __syncthreads();

    // scores: 4 lanes per s, split K=512 into 4x128
    const int s = tid >> 2, qd = tid & 3;
    const float* crow = ctx + (size_t)s*BH + b*Hd;
    float acc = 0.f;
    const int h0 = qd*128;
    #pragma unroll 8
    for (int h = h0; h < h0+128; ++h) acc = fmaf(qs[h], crow[h], acc);
    acc += __shfl_xor_sync(0xffffffffu, acc, 1);
    acc += __shfl_xor_sync(0xffffffffu, acc, 2);
    if (qd == 0) sc[s] = acc;
    __syncthreads();

    // softmax over S=64 by warp 0
    if (tid < 32){
        float v0 = sc[tid], v1 = sc[tid+32];
        float m = fmaxf(v0, v1);
        #pragma unroll
        for (int o=16; o; o>>=1) m = fmaxf(m, __shfl_xor_sync(0xffffffffu, m, o));
        float e0 = __expf(v0 - m), e1 = __expf(v1 - m);
        float ssum = e0 + e1;
        #pragma unroll
        for (int o=16; o; o>>=1) ssum += __shfl_xor_sync(0xffffffffu, ssum, o);
        float inv = 1.f/ssum;
        al[tid]    = e0*inv;  al[tid+32] = e1*inv;
        dout[OFF_AT + t*Bz*Sl + b*Sl + tid]      = e0*inv;
        dout[OFF_AT + t*Bz*Sl + b*Sl + tid + 32] = e1*inv;
    }
    __syncthreads();

    // cvec[h] = sum_s al[s]*ctx[s,b,h]
    for (int h = tid; h < Hd; h += 256){
        float a = 0.f;
        const float* cp = ctx + b*Hd + h;
        #pragma unroll 8
        for (int s2=0; s2<Sl; ++s2) a = fmaf(al[s2], cp[(size_t)s2*BH], a);
        g_cvec[b*Hd + h] = a;
    }
}

// ---------------------------------------------------------------------------
// Kernel O: attn_h = tanh([cvec | h1n] @ Wout^T) -> outputs[t], feed, (feedf)
// grid=64, tile 64b x 8j, K=1024.
// ---------------------------------------------------------------------------
__global__ __launch_bounds__(256) void kO(const float* __restrict__ Wout,
                                          float* __restrict__ dout, int t)
{
    __shared__ float xs[32][64];
    __shared__ float ws[32][8];
    const int tid = threadIdx.x;
    const int jb  = blockIdx.x << 3;
    const int tb = tid & 31, tc = tid >> 5;
    const int lb = tid >> 2, lk = (tid & 3) << 3;
    const int lj = tid >> 5, lk2 = tid & 31;
    float a0=0.f, a1=0.f;
    const float* h1n = g_h1[(t&1)^1];
    for (int kc=0; kc<32; ++kc){
        const float* xsrc = (kc<16) ? g_cvec + lb*Hd + (kc<<5)
                                    : h1n    + lb*Hd + ((kc-16)<<5);
        float4 v0 = *(const float4*)(xsrc+lk);
        float4 v1 = *(const float4*)(xsrc+lk+4);
        float wv = Wout[(size_t)(jb+lj)*1024 + (kc<<5) + lk2];
        xs[lk+0][lb]=v0.x; xs[lk+1][lb]=v0.y; xs[lk+2][lb]=v0.z; xs[lk+3][lb]=v0.w;
        xs[lk+4][lb]=v1.x; xs[lk+5][lb]=v1.y; xs[lk+6][lb]=v1.z; xs[lk+7][lb]=v1.w;
        ws[lk2][lj]=wv;
        __syncthreads();
        #pragma unroll
        for (int kk=0; kk<32; ++kk){
            float2 xv = *(const float2*)&xs[kk][tb<<1];
            float w  = ws[kk][tc];
            a0 = fmaf(xv.x, w, a0);
            a1 = fmaf(xv.y, w, a1);
        }
        __syncthreads();
    }
    const int h  = jb + tc;
    const int b0 = tb*2, b1 = b0+1;
    float o0 = tanhf(a0), o1 = tanhf(a1);
    g_feed[b0*Hd + h] = o0;
    g_feed[b1*Hd + h] = o1;
    dout[t*BH + b0*Hd + h] = o0;
    dout[t*BH + b1*Hd + h] = o1;
    if (t == Tt-1){
        dout[OFF_FF + b0*Hd + h] = o0;
        dout[OFF_FF + b1*Hd + h] = o1;
    }
}

// ---------------------------------------------------------------------------
extern "C" void kernel_launch(void* const* d_in, const int* in_sizes, int n_in,
                              void* d_out, int out_size)
{
    const int*   toks = (const int*)  d_in[0];
    // d_in[1] = src (unused by the reference computation)
    const float* ctx  = (const float*)d_in[2];
    const float* h0   = (const float*)d_in[3];
    const float* c0   = (const float*)d_in[4];
    const float* feed = (const float*)d_in[5];
    const float* emb  = (const float*)d_in[6];
    const float* Wih0 = (const float*)d_in[7];
    const float* Whh0 = (const float*)d_in[8];
    const float* bih0 = (const float*)d_in[9];
    const float* bhh0 = (const float*)d_in[10];
    const float* Wih1 = (const float*)d_in[11];
    const float* Whh1 = (const float*)d_in[12];
    const float* bih1 = (const float*)d_in[13];
    const float* bhh1 = (const float*)d_in[14];
    const float* Wa   = (const float*)d_in[15];
    const float* Wout = (const float*)d_in[16];
    float* dout = (float*)d_out;

    kInit<<<BH/256, 256>>>(h0, c0, feed);
    for (int t = 0; t < Tt; ++t){
        kA<<<128, 256>>>(toks, emb, Wih0, Whh0, bih0, bhh0, dout, t);
        kB<<<128, 256>>>(Wih1, Whh1, bih1, bhh1, dout, t);
        kQ<<<64, 256>>>(Wa, t);
        kS<<<64, 256>>>(ctx, dout, t);
        kO<<<64, 256>>>(Wout, dout, t);
    }
}

// round 4
// speedup vs baseline: 1.9550x; 1.9550x over previous
#include <cuda_runtime.h>
#include <math.h>

// Problem constants
#define Bz 64
#define Hd 512
#define Sl 64
#define Tt 32
#define BH (Bz*Hd)
#define NB 128        // persistent grid size (all co-resident, <=148 SMs)

// Output layout (flattened, reference return order)
#define OFF_AT 1048576
#define OFF_HF 1179648
#define OFF_CF 1245184
#define OFF_FF 1310720

// ---------------------------------------------------------------------------
// Persistent state (__device__ globals; no allocation allowed)
// ---------------------------------------------------------------------------
__device__ float g_h0[2][BH], g_h1[2][BH];
__device__ float g_c0[BH], g_c1[BH], g_feed[BH], g_cvec[BH];
__device__ float g_ctxW[Sl*Bz*Hd];       // [s][b][k] = sum_j ctx[s,b,j]*Wa[j,k]
__device__ float g_g0[2][Bz*4*Hd];       // gates0 split-K partials [ks][b][4H]
__device__ float g_g1[2][Bz*4*Hd];       // gates1 partials
__device__ float g_op[8][BH];            // Wout partials [ks][b][H]
__device__ unsigned g_barcnt = 0u;
__device__ unsigned g_bargen = 0u;

__device__ __forceinline__ float sigf(float x){ return 1.0f/(1.0f+__expf(-x)); }

// Grid-wide barrier: all NB blocks arrive; tid0 of last arriver bumps gen to
// 'target'. gpu-scope fences (CCTL.IVALL on sm_103a) give cross-SM visibility.
__device__ __forceinline__ void gridbar_to(unsigned target){
    __threadfence();
    __syncthreads();
    if (threadIdx.x == 0){
        if (atomicAdd(&g_barcnt, 1u) == (unsigned)(NB-1)){
            g_barcnt = 0u;
            __threadfence();
            atomicExch(&g_bargen, target);
        } else {
            while (*(volatile unsigned*)&g_bargen != target) { }
        }
    }
    __syncthreads();
    __threadfence();
}

// ---------------------------------------------------------------------------
// Generic 64b x 32j tile GEMM, 256 threads, micro-tile 2b x 4j (8 accums).
// K processed in chunks of 32 with register prefetch (LDG overlapped with
// FFMA of current chunk). x staged as xs[k][b], w staged as ws[k][j] (pad 36
// so float4 reads stay 16B-aligned and STS is conflict-free).
// FX(c,row) -> const float* base of 32-float k-chunk c for x-row `row`
// FW(c,col) -> const float* base of k-chunk c for output column `col`,
//              elements strided by LDW (LDW=1: row-major W, vectorized).
// ---------------------------------------------------------------------------
template<int LDW, class FX, class FW>
__device__ __forceinline__ void tile_gemm(float a[2][4], FX fx, FW fw, int nch,
                                          float (*xs)[64], float (*ws)[36])
{
    const int tid = threadIdx.x;
    const int tb = tid & 31, tc = tid >> 5;     // 32 b-pairs x 8 j-quads
    const int lb = tid >> 2, lk = (tid & 3) << 3;   // x loader
    const int wj = tid & 31, wk = (tid >> 5) << 2;  // w loader
    float4 xv0, xv1; float w0,w1,w2,w3;
    {
        const float* xp = fx(0, lb);
        xv0 = *(const float4*)(xp + lk);
        xv1 = *(const float4*)(xp + lk + 4);
        const float* wp = fw(0, wj) + (size_t)wk * LDW;
        if constexpr (LDW == 1){ float4 t4 = *(const float4*)wp; w0=t4.x; w1=t4.y; w2=t4.z; w3=t4.w; }
        else { w0=wp[0]; w1=wp[LDW]; w2=wp[2*LDW]; w3=wp[3*LDW]; }
    }
    for (int c = 0; c < nch; ++c){
        xs[lk+0][lb]=xv0.x; xs[lk+1][lb]=xv0.y; xs[lk+2][lb]=xv0.z; xs[lk+3][lb]=xv0.w;
        xs[lk+4][lb]=xv1.x; xs[lk+5][lb]=xv1.y; xs[lk+6][lb]=xv1.z; xs[lk+7][lb]=xv1.w;
        ws[wk+0][wj]=w0; ws[wk+1][wj]=w1; ws[wk+2][wj]=w2; ws[wk+3][wj]=w3;
        __syncthreads();
        if (c+1 < nch){
            const float* xp = fx(c+1, lb);
            xv0 = *(const float4*)(xp + lk);
            xv1 = *(const float4*)(xp + lk + 4);
            const float* wp = fw(c+1, wj) + (size_t)wk * LDW;
            if constexpr (LDW == 1){ float4 t4 = *(const float4*)wp; w0=t4.x; w1=t4.y; w2=t4.z; w3=t4.w; }
            else { w0=wp[0]; w1=wp[LDW]; w2=wp[2*LDW]; w3=wp[3*LDW]; }
        }
        #pragma unroll
        for (int kk = 0; kk < 32; ++kk){
            float2 x2 = *(const float2*)&xs[kk][tb<<1];
            float4 w4 = *(const float4*)&ws[kk][tc<<2];
            a[0][0]=fmaf(x2.x,w4.x,a[0][0]); a[0][1]=fmaf(x2.x,w4.y,a[0][1]);
            a[0][2]=fmaf(x2.x,w4.z,a[0][2]); a[0][3]=fmaf(x2.x,w4.w,a[0][3]);
            a[1][0]=fmaf(x2.y,w4.x,a[1][0]); a[1][1]=fmaf(x2.y,w4.y,a[1][1]);
            a[1][2]=fmaf(x2.y,w4.z,a[1][2]); a[1][3]=fmaf(x2.y,w4.w,a[1][3]);
        }
        __syncthreads();
    }
}

// ---------------------------------------------------------------------------
// The single persistent kernel.
// ---------------------------------------------------------------------------
__global__ __launch_bounds__(256, 1) void kMain(
    const int*   __restrict__ toks, const float* __restrict__ ctx,
    const float* __restrict__ h0i,  const float* __restrict__ c0i,
    const float* __restrict__ feedi,const float* __restrict__ emb,
    const float* __restrict__ Wih0, const float* __restrict__ Whh0,
    const float* __restrict__ bih0, const float* __restrict__ bhh0,
    const float* __restrict__ Wih1, const float* __restrict__ Whh1,
    const float* __restrict__ bih1, const float* __restrict__ bhh1,
    const float* __restrict__ Wa,   const float* __restrict__ Wout,
    float* __restrict__ dout)
{
    __shared__ __align__(16) float xs[32][64];
    __shared__ __align__(16) float ws[32][36];
    __shared__ float sSc[64], sAl[64];
    const int blk = blockIdx.x, tid = threadIdx.x;
    const int tb = tid & 31, tc = tid >> 5;

    unsigned bgen = 0u;
    if (tid == 0) bgen = *(volatile unsigned*)&g_bargen;

    // ---- Init persistent state (exactly one element per thread) ----
    {
        int i = blk*256 + tid;   // NB*256 == BH
        g_h0[0][i] = h0i[i];      g_h1[0][i] = h0i[BH + i];
        g_c0[i]    = c0i[i];      g_c1[i]    = c0i[BH + i];
        g_feed[i]  = feedi[i];
    }

    // ---- One-time: ctxW[sb][k] = sum_j ctx[sb][j] * Wa[j][k] ----
    // 1024 tiles (64 row-tiles x 16 col-tiles), 8 per block.
    for (int it = 0; it < 8; ++it){
        int tile = blk + it*NB;
        int sb0 = (tile >> 4) << 6;     // 64 sb-rows per tile
        int kc0 = (tile & 15) << 5;     // 32 k-cols per tile
        float a[2][4] = {};
        auto fx = [&](int c, int row) -> const float* {
            return ctx + (size_t)(sb0 + row)*Hd + (c<<5);
        };
        auto fw = [&](int c, int col) -> const float* {
            return Wa + (size_t)(c<<5)*Hd + kc0 + col;   // transposed access, stride Hd
        };
        tile_gemm<Hd>(a, fx, fw, 16, xs, ws);
        #pragma unroll
        for (int r = 0; r < 2; ++r){
            float4 v = make_float4(a[r][0],a[r][1],a[r][2],a[r][3]);
            *(float4*)&g_ctxW[(size_t)(sb0 + tb*2 + r)*Hd + kc0 + (tc<<2)] = v;
        }
    }
    gridbar_to(++bgen);

    // ---- Time loop ----
    for (int t = 0; t < Tt; ++t){
        const int p = t & 1;
        const float* h0p = g_h0[p];
        const float* h1p = g_h1[p];
        float* h0n = g_h0[p^1];
        float* h1n = g_h1[p^1];

        // Phase A1: gates0 partials. 64 j-tiles x 2 K-splits (K=768 each).
        {
            const int ks = blk >> 6, j0 = (blk & 63) << 5;
            const int kbase = ks * 768;
            int mytok = 0;
            if (ks == 0) mytok = toks[t*Bz + (tid >> 2)];
            float a[2][4] = {};
            auto fx = [&](int c, int row) -> const float* {
                int kg = kbase + (c<<5);
                if (kg < 512)  return emb + (size_t)mytok*512 + kg;
                if (kg < 1024) return (const float*)g_feed + (size_t)row*Hd + (kg - 512);
                return h0p + (size_t)row*Hd + (kg - 1024);
            };
            auto fw = [&](int c, int col) -> const float* {
                int kg = kbase + (c<<5);
                int j  = j0 + col;
                if (kg < 1024) return Wih0 + (size_t)j*1024 + kg;
                return Whh0 + (size_t)j*512 + (kg - 1024);
            };
            tile_gemm<1>(a, fx, fw, 24, xs, ws);
            float* gp = g_g0[ks];
            #pragma unroll
            for (int r = 0; r < 2; ++r){
                float4 v = make_float4(a[r][0],a[r][1],a[r][2],a[r][3]);
                *(float4*)&gp[(size_t)(tb*2 + r)*2048 + j0 + (tc<<2)] = v;
            }
        }
        gridbar_to(++bgen);

        // Phase A2: combine partials + bias + LSTM cell 0
        {
            int idx = blk*256 + tid;             // == b*512 + u
            int u = idx & 511, b = idx >> 9;
            const float* G0 = g_g0[0] + (size_t)b*2048;
            const float* G1 = g_g0[1] + (size_t)b*2048;
            float iv = G0[u]      + G1[u]      + bih0[u]      + bhh0[u];
            float fv = G0[512+u]  + G1[512+u]  + bih0[512+u]  + bhh0[512+u];
            float gv = G0[1024+u] + G1[1024+u] + bih0[1024+u] + bhh0[1024+u];
            float ov = G0[1536+u] + G1[1536+u] + bih0[1536+u] + bhh0[1536+u];
            float cn = sigf(fv)*g_c0[idx] + sigf(iv)*tanhf(gv);
            float hn = sigf(ov)*tanhf(cn);
            g_c0[idx] = cn;  h0n[idx] = hn;
            if (t == Tt-1){ dout[OFF_HF + idx] = hn; dout[OFF_CF + idx] = cn; }
        }
        gridbar_to(++bgen);

        // Phase B1: gates1 partials. K=1024 split: ks=0 -> h0n/Wih1, ks=1 -> h1p/Whh1.
        {
            const int ks = blk >> 6, j0 = (blk & 63) << 5;
            const float* xb = ks ? h1p : (const float*)h0n;
            const float* wb = ks ? Whh1 : Wih1;
            float a[2][4] = {};
            auto fx = [&](int c, int row) -> const float* {
                return xb + (size_t)row*Hd + (c<<5);
            };
            auto fw = [&](int c, int col) -> const float* {
                return wb + (size_t)(j0 + col)*Hd + (c<<5);
            };
            tile_gemm<1>(a, fx, fw, 16, xs, ws);
            float* gp = g_g1[ks];
            #pragma unroll
            for (int r = 0; r < 2; ++r){
                float4 v = make_float4(a[r][0],a[r][1],a[r][2],a[r][3]);
                *(float4*)&gp[(size_t)(tb*2 + r)*2048 + j0 + (tc<<2)] = v;
            }
        }
        gridbar_to(++bgen);

        // Phase B2: cell 1
        {
            int idx = blk*256 + tid;
            int u = idx & 511, b = idx >> 9;
            const float* G0 = g_g1[0] + (size_t)b*2048;
            const float* G1 = g_g1[1] + (size_t)b*2048;
            float iv = G0[u]      + G1[u]      + bih1[u]      + bhh1[u];
            float fv = G0[512+u]  + G1[512+u]  + bih1[512+u]  + bhh1[512+u];
            float gv = G0[1024+u] + G1[1024+u] + bih1[1024+u] + bhh1[1024+u];
            float ov = G0[1536+u] + G1[1536+u] + bih1[1536+u] + bhh1[1536+u];
            float cn = sigf(fv)*g_c1[idx] + sigf(iv)*tanhf(gv);
            float hn = sigf(ov)*tanhf(cn);
            g_c1[idx] = cn;  h1n[idx] = hn;
            if (t == Tt-1){ dout[OFF_HF + BH + idx] = hn; dout[OFF_CF + BH + idx] = cn; }
        }
        gridbar_to(++bgen);

        // Phase S: scores via ctxW, softmax, attns out, cvec. Blocks 0..63.
        if (blk < Bz){
            const int b = blk;
            float* qs = &xs[0][0];                 // 512 floats, reuse smem
            qs[tid]       = h1n[b*Hd + tid];
            qs[tid + 256] = h1n[b*Hd + 256 + tid];
            __syncthreads();
            const int s = tid >> 2, qd = tid & 3;
            const float* crow = g_ctxW + (size_t)(s*Bz + b)*Hd + qd*128;
            const float* qp = qs + qd*128;
            float acc = 0.f;
            #pragma unroll 16
            for (int i = 0; i < 128; ++i) acc = fmaf(qp[i], crow[i], acc);
            acc += __shfl_xor_sync(0xffffffffu, acc, 1);
            acc += __shfl_xor_sync(0xffffffffu, acc, 2);
            if (qd == 0) sSc[s] = acc;
            __syncthreads();
            if (tid < 32){
                float v0 = sSc[tid], v1 = sSc[tid+32];
                float m = fmaxf(v0, v1);
                #pragma unroll
                for (int o = 16; o; o >>= 1) m = fmaxf(m, __shfl_xor_sync(0xffffffffu, m, o));
                float e0 = __expf(v0 - m), e1 = __expf(v1 - m);
                float ssum = e0 + e1;
                #pragma unroll
                for (int o = 16; o; o >>= 1) ssum += __shfl_xor_sync(0xffffffffu, ssum, o);
                float inv = 1.f/ssum;
                sAl[tid] = e0*inv;  sAl[tid+32] = e1*inv;
                dout[OFF_AT + t*Bz*Sl + b*Sl + tid]      = e0*inv;
                dout[OFF_AT + t*Bz*Sl + b*Sl + tid + 32] = e1*inv;
            }
            __syncthreads();
            for (int h = tid; h < Hd; h += 256){
                float a2 = 0.f;
                const float* cp = ctx + (size_t)b*Hd + h;
                #pragma unroll 8
                for (int s2 = 0; s2 < Sl; ++s2) a2 = fmaf(sAl[s2], cp[(size_t)s2*BH], a2);
                g_cvec[b*Hd + h] = a2;
            }
        }
        gridbar_to(++bgen);

        // Phase O1: Wout partials. 16 j-tiles x 8 K-splits (K=128 each).
        {
            const int ks = blk >> 4, j0 = (blk & 15) << 5;
            const int kbase = ks << 7;
            const float* xb   = (ks < 4) ? (const float*)g_cvec : (const float*)h1n;
            const int    koff = (ks < 4) ? kbase : (kbase - 512);
            float a[2][4] = {};
            auto fx = [&](int c, int row) -> const float* {
                return xb + (size_t)row*Hd + koff + (c<<5);
            };
            auto fw = [&](int c, int col) -> const float* {
                return Wout + (size_t)(j0 + col)*1024 + kbase + (c<<5);
            };
            tile_gemm<1>(a, fx, fw, 4, xs, ws);
            float* gp = g_op[ks];
            #pragma unroll
            for (int r = 0; r < 2; ++r){
                float4 v = make_float4(a[r][0],a[r][1],a[r][2],a[r][3]);
                *(float4*)&gp[(size_t)(tb*2 + r)*Hd + j0 + (tc<<2)] = v;
            }
        }
        gridbar_to(++bgen);

        // Phase O2: combine 8 partials + tanh -> feed, outputs[t], feedf
        {
            int idx = blk*256 + tid;
            float s = 0.f;
            #pragma unroll
            for (int ks = 0; ks < 8; ++ks) s += g_op[ks][idx];
            float o = tanhf(s);
            g_feed[idx] = o;
            dout[t*BH + idx] = o;
            if (t == Tt-1) dout[OFF_FF + idx] = o;
        }
        gridbar_to(++bgen);
    }
}

// ---------------------------------------------------------------------------
extern "C" void kernel_launch(void* const* d_in, const int* in_sizes, int n_in,
                              void* d_out, int out_size)
{
    const int*   toks = (const int*)  d_in[0];
    // d_in[1] = src (unused by the reference computation)
    const float* ctx  = (const float*)d_in[2];
    const float* h0   = (const float*)d_in[3];
    const float* c0   = (const float*)d_in[4];
    const float* feed = (const float*)d_in[5];
    const float* emb  = (const float*)d_in[6];
    const float* Wih0 = (const float*)d_in[7];
    const float* Whh0 = (const float*)d_in[8];
    const float* bih0 = (const float*)d_in[9];
    const float* bhh0 = (const float*)d_in[10];
    const float* Wih1 = (const float*)d_in[11];
    const float* Whh1 = (const float*)d_in[12];
    const float* bih1 = (const float*)d_in[13];
    const float* bhh1 = (const float*)d_in[14];
    const float* Wa   = (const float*)d_in[15];
    const float* Wout = (const float*)d_in[16];
    float* dout = (float*)d_out;

    kMain<<<NB, 256>>>(toks, ctx, h0, c0, feed, emb,
                       Wih0, Whh0, bih0, bhh0,
                       Wih1, Whh1, bih1, bhh1,
                       Wa, Wout, dout);
}